// round 7
// baseline (speedup 1.0000x reference)
#include <cuda_runtime.h>
#include <cuda_bf16.h>
#include <cstdint>

#define NN   10000
#define EE   320000
#define GG   64
#define NIN  64
#define EIN  16
#define HID  256

// ---------------- helpers ------------------------------------------------------------
__device__ __forceinline__ unsigned tf32_rna_u(float x) {
    unsigned r;
    asm("cvt.rna.tf32.f32 %0, %1;" : "=r"(r) : "f"(x));
    return r;
}
__device__ __forceinline__ float tf32_rna(float x) {
    return __uint_as_float(tf32_rna_u(x));
}
// m16n8k8 tf32 mma, D = A*B + D (fp32 accumulate)
__device__ __forceinline__ void mma8(float c[4], unsigned a0, unsigned a1, unsigned a2,
                                     unsigned a3, unsigned b0, unsigned b1) {
    asm volatile(
        "mma.sync.aligned.m16n8k8.row.col.f32.tf32.tf32.f32 "
        "{%0,%1,%2,%3}, {%4,%5,%6,%7}, {%8,%9}, {%0,%1,%2,%3};"
        : "+f"(c[0]), "+f"(c[1]), "+f"(c[2]), "+f"(c[3])
        : "r"(a0), "r"(a1), "r"(a2), "r"(a3), "r"(b0), "r"(b1));
}

// ---------------- scratch (__device__ globals; no allocation allowed) ----------------
__device__ __align__(16) float g_W0h[HID * NIN], g_W0l[HID * NIN];  // (we2@l0_lw) hi/lo
__device__ __align__(16) float g_b0f[NIN];
__device__ __align__(16) float g_W1h[HID * HID], g_W1l[HID * HID];  // (we2@l1_lw) hi/lo
__device__ __align__(16) float g_b1f[HID];
__device__ __align__(16) float g_Hh[(size_t)EE * HID];  // hidden hi (tf32-rounded)
__device__ __align__(16) float g_Hl[(size_t)EE * HID];  // hidden residual
__device__ __align__(16) float g_agg0[NN * NIN];
__device__ __align__(16) float g_agg1[NN * HID];
__device__ __align__(16) float g_x1[NN * HID];
__device__ __align__(16) float g_tmp[NN * HID];
__device__ __align__(16) float g_x2[NN * HID];
__device__ float g_cnt[GG];

// ---------------- weight pre-products + tf32 split -----------------------------------
__global__ void fuse_weights(const float* __restrict__ we2, const float* __restrict__ be2,
                             const float* __restrict__ l0_lw, const float* __restrict__ l0_lb,
                             const float* __restrict__ l1_lw, const float* __restrict__ l1_lb) {
    __shared__ float s_w[HID];
    int k = blockIdx.x;
    int n = threadIdx.x;
    s_w[n] = we2[k * HID + n];
    __syncthreads();
    float acc = 0.f;
    for (int j = 0; j < HID; j++) acc += s_w[j] * l1_lw[j * HID + n];
    float h = tf32_rna(acc);
    g_W1h[k * HID + n] = h;
    g_W1l[k * HID + n] = acc - h;
    if (n < NIN) {
        float a0 = 0.f;
        for (int j = 0; j < HID; j++) a0 += s_w[j] * l0_lw[j * NIN + n];
        float h0 = tf32_rna(a0);
        g_W0h[k * NIN + n] = h0;
        g_W0l[k * NIN + n] = a0 - h0;
    }
    if (k == 0) {
        float bb = 0.f;
        for (int j = 0; j < HID; j++) bb += be2[j] * l1_lw[j * HID + n];
        g_b1f[n] = bb + l1_lb[n];
        if (n < NIN) {
            float b0 = 0.f;
            for (int j = 0; j < HID; j++) b0 += be2[j] * l0_lw[j * NIN + n];
            g_b0f[n] = b0 + l0_lb[n];
        }
    }
}

// ---------------- hidden = relu(ea@we1+be1), split hi/lo, materialized ---------------
// block: 8 edges x 32 lanes; lane covers cols {4l..4l+3} and {128+4l..128+4l+3}
__global__ void __launch_bounds__(256) hidden_split(const float* __restrict__ ea,
                                                    const float* __restrict__ we1,
                                                    const float* __restrict__ be1) {
    __shared__ __align__(16) float sw[EIN][HID];
    __shared__ __align__(16) float sb[HID];
    __shared__ __align__(16) float sea[8][EIN];
    const int tid = threadIdx.x;
    const int e0 = blockIdx.x * 8;

    for (int i = tid; i < EIN * HID / 4; i += 256)
        reinterpret_cast<float4*>(&sw[0][0])[i] = reinterpret_cast<const float4*>(we1)[i];
    if (tid < HID) sb[tid] = be1[tid];
    if (tid < 128) sea[tid / EIN][tid % EIN] = ea[(size_t)(e0 + tid / EIN) * EIN + tid % EIN];
    __syncthreads();

    const int e = tid >> 5, l = tid & 31;
    float a[EIN];
#pragma unroll
    for (int k = 0; k < EIN; k++) a[k] = sea[e][k];

    float4 v0 = *reinterpret_cast<float4*>(&sb[4 * l]);
    float4 v1 = *reinterpret_cast<float4*>(&sb[128 + 4 * l]);
#pragma unroll
    for (int k = 0; k < EIN; k++) {
        float ak = a[k];
        float4 w0 = *reinterpret_cast<float4*>(&sw[k][4 * l]);
        float4 w1 = *reinterpret_cast<float4*>(&sw[k][128 + 4 * l]);
        v0.x = fmaf(ak, w0.x, v0.x); v0.y = fmaf(ak, w0.y, v0.y);
        v0.z = fmaf(ak, w0.z, v0.z); v0.w = fmaf(ak, w0.w, v0.w);
        v1.x = fmaf(ak, w1.x, v1.x); v1.y = fmaf(ak, w1.y, v1.y);
        v1.z = fmaf(ak, w1.z, v1.z); v1.w = fmaf(ak, w1.w, v1.w);
    }
    v0.x = fmaxf(v0.x, 0.f); v0.y = fmaxf(v0.y, 0.f);
    v0.z = fmaxf(v0.z, 0.f); v0.w = fmaxf(v0.w, 0.f);
    v1.x = fmaxf(v1.x, 0.f); v1.y = fmaxf(v1.y, 0.f);
    v1.z = fmaxf(v1.z, 0.f); v1.w = fmaxf(v1.w, 0.f);

    float4 h0, h1, r0, r1;
    h0.x = tf32_rna(v0.x); r0.x = v0.x - h0.x;
    h0.y = tf32_rna(v0.y); r0.y = v0.y - h0.y;
    h0.z = tf32_rna(v0.z); r0.z = v0.z - h0.z;
    h0.w = tf32_rna(v0.w); r0.w = v0.w - h0.w;
    h1.x = tf32_rna(v1.x); r1.x = v1.x - h1.x;
    h1.y = tf32_rna(v1.y); r1.y = v1.y - h1.y;
    h1.z = tf32_rna(v1.z); r1.z = v1.z - h1.z;
    h1.w = tf32_rna(v1.w); r1.w = v1.w - h1.w;

    size_t base = (size_t)(e0 + e) * HID;
    *reinterpret_cast<float4*>(g_Hh + base + 4 * l)       = h0;
    *reinterpret_cast<float4*>(g_Hh + base + 128 + 4 * l) = h1;
    *reinterpret_cast<float4*>(g_Hl + base + 4 * l)       = r0;
    *reinterpret_cast<float4*>(g_Hl + base + 128 + 4 * l) = r1;
}

__global__ void zero_aggs() {
    int i = blockIdx.x * 256 + threadIdx.x;
    int st = gridDim.x * 256;
    for (int j = i; j < NN * HID; j += st) g_agg1[j] = 0.f;
    for (int j = i; j < NN * NIN; j += st) g_agg0[j] = 0.f;
}

// ---------------- conv GEMM via tf32x3 mma + fused gather/relu/atomic epilogue -------
// e_proj[TE x TN] = H[TE x 256] @ Wf[256 x TN]; msg = relu(x[src]+e_proj+bias);
// atomicAdd into agg[dst]. CONV=0: TN=CIN=64; CONV=1: CIN=256, TN=128, grid.y=2.
template <int CONV>
__global__ void __launch_bounds__(256) conv_mma(const int* __restrict__ src,
                                                const int* __restrict__ dst,
                                                const float* __restrict__ xin_param) {
    constexpr int CIN = CONV ? HID : NIN;
    constexpr int TN  = CONV ? 128 : 64;
    constexpr int TE = 128, KC = 16;
    constexpr int WN = TN / 2;   // n-cols per warp
    constexpr int NF = WN / 8;   // n-frags per warp
    const float* Wh = CONV ? g_W1h : g_W0h;
    const float* Wl = CONV ? g_W1l : g_W0l;
    const float* bf = CONV ? g_b1f : g_b0f;
    const float* xp = CONV ? g_x1 : xin_param;
    float* agg      = CONV ? g_agg1 : g_agg0;

    __shared__ float sAh[TE][KC + 4], sAl[TE][KC + 4];
    __shared__ float sBh[KC][TN + 4], sBl[KC][TN + 4];
    __shared__ int s_src[TE], s_dst[TE];

    const int tid = threadIdx.x;
    const int lane = tid & 31, w = tid >> 5;
    const int g = lane >> 2, tig = lane & 3;
    const int eW = (w >> 1) * 32, nW = (w & 1) * WN;
    const int e0 = blockIdx.x * TE, n0 = blockIdx.y * TN;

    if (tid < TE) {
        s_src[tid] = src[e0 + tid];
        s_dst[tid] = dst[e0 + tid];
    }

    float acc[2][NF][4];
#pragma unroll
    for (int ti = 0; ti < 2; ti++)
#pragma unroll
        for (int ni = 0; ni < NF; ni++)
#pragma unroll
            for (int c = 0; c < 4; c++) acc[ti][ni][c] = 0.f;

    for (int kc = 0; kc < HID; kc += KC) {
        __syncthreads();
        {   // A tile: 128 edges x 16 k (hi + lo)
            int e = tid >> 1, kh = (tid & 1) * 8;
            const float4* gh =
                reinterpret_cast<const float4*>(g_Hh + (size_t)(e0 + e) * HID + kc + kh);
            const float4* gl =
                reinterpret_cast<const float4*>(g_Hl + (size_t)(e0 + e) * HID + kc + kh);
            *reinterpret_cast<float4*>(&sAh[e][kh])     = gh[0];
            *reinterpret_cast<float4*>(&sAh[e][kh + 4]) = gh[1];
            *reinterpret_cast<float4*>(&sAl[e][kh])     = gl[0];
            *reinterpret_cast<float4*>(&sAl[e][kh + 4]) = gl[1];
        }
        // B tile: 16 k x TN (hi + lo)
        for (int i = tid; i < KC * TN / 4; i += 256) {
            int k = i / (TN / 4), nq = (i % (TN / 4)) * 4;
            *reinterpret_cast<float4*>(&sBh[k][nq]) =
                *reinterpret_cast<const float4*>(Wh + (size_t)(kc + k) * CIN + n0 + nq);
            *reinterpret_cast<float4*>(&sBl[k][nq]) =
                *reinterpret_cast<const float4*>(Wl + (size_t)(kc + k) * CIN + n0 + nq);
        }
        __syncthreads();
#pragma unroll
        for (int ks = 0; ks < KC / 8; ks++) {
#pragma unroll
            for (int ti = 0; ti < 2; ti++) {
                int er = eW + ti * 16;
                int kk = ks * 8 + tig;
                unsigned ah0 = __float_as_uint(sAh[er + g][kk]);
                unsigned ah1 = __float_as_uint(sAh[er + 8 + g][kk]);
                unsigned ah2 = __float_as_uint(sAh[er + g][kk + 4]);
                unsigned ah3 = __float_as_uint(sAh[er + 8 + g][kk + 4]);
                unsigned al0 = __float_as_uint(sAl[er + g][kk]);
                unsigned al1 = __float_as_uint(sAl[er + 8 + g][kk]);
                unsigned al2 = __float_as_uint(sAl[er + g][kk + 4]);
                unsigned al3 = __float_as_uint(sAl[er + 8 + g][kk + 4]);
#pragma unroll
                for (int ni = 0; ni < NF; ni++) {
                    int nn = nW + ni * 8 + g;
                    unsigned bh0 = __float_as_uint(sBh[kk][nn]);
                    unsigned bh1 = __float_as_uint(sBh[kk + 4][nn]);
                    unsigned bl0 = __float_as_uint(sBl[kk][nn]);
                    unsigned bl1 = __float_as_uint(sBl[kk + 4][nn]);
                    mma8(acc[ti][ni], ah0, ah1, ah2, ah3, bh0, bh1);
                    mma8(acc[ti][ni], ah0, ah1, ah2, ah3, bl0, bl1);
                    mma8(acc[ti][ni], al0, al1, al2, al3, bh0, bh1);
                }
            }
        }
    }

    // epilogue: c0/c1 at edge er+g, cols 2tig/2tig+1; c2/c3 at edge er+8+g
#pragma unroll
    for (int ti = 0; ti < 2; ti++) {
        int er = eW + ti * 16 + g;
        int s0 = s_src[er], d0 = s_dst[er];
        int s1 = s_src[er + 8], d1 = s_dst[er + 8];
#pragma unroll
        for (int ni = 0; ni < NF; ni++) {
            int ncl = nW + ni * 8 + 2 * tig;  // block-local col
            int nc = n0 + ncl;                 // global col
            float b0v = bf[nc], b1v = bf[nc + 1];
            float2 x0 = *reinterpret_cast<const float2*>(xp + (size_t)s0 * CIN + nc);
            float2 x1 = *reinterpret_cast<const float2*>(xp + (size_t)s1 * CIN + nc);
            float* a0p = agg + (size_t)d0 * CIN + nc;
            float* a1p = agg + (size_t)d1 * CIN + nc;
            atomicAdd(a0p,     fmaxf(acc[ti][ni][0] + b0v + x0.x, 0.f));
            atomicAdd(a0p + 1, fmaxf(acc[ti][ni][1] + b1v + x0.y, 0.f));
            atomicAdd(a1p,     fmaxf(acc[ti][ni][2] + b0v + x1.x, 0.f));
            atomicAdd(a1p + 1, fmaxf(acc[ti][ni][3] + b1v + x1.y, 0.f));
        }
    }
}

// ---------------- node MLP GEMM (fp32, unchanged from passing R6 kernel) -------------
template <int K, int SEL>
__global__ void __launch_bounds__(256) node_mlp(const float* __restrict__ xin_param,
                                                const float* __restrict__ W,
                                                const float* __restrict__ b) {
    constexpr int TM = 64, TN = 128, KC = 32;
    constexpr bool HAS2 = (SEL == 0 || SEL == 2);
    const float* A1 = (SEL == 0) ? xin_param : (SEL == 2 ? g_x1 : g_tmp);
    const float* A2 = (SEL == 0) ? g_agg0 : g_agg1;
    float* out = (SEL == 0 || SEL == 2) ? g_tmp : (SEL == 1 ? g_x1 : g_x2);

    __shared__ float s_A[KC][TM + 1];
    __shared__ __align__(16) float s_B[KC][TN];
    int tid = threadIdx.x, cx = tid & 31, cy = tid >> 5;
    int m0 = blockIdx.x * TM, n0 = blockIdx.y * TN;
    float acc[8][4] = {};

    for (int kc = 0; kc < K; kc += KC) {
        __syncthreads();
        for (int i = tid; i < KC * TM; i += 256) {
            int k = i % KC, m = i / KC, gm = m0 + m;
            float v = 0.f;
            if (gm < NN) {
                v = A1[(size_t)gm * K + kc + k];
                if constexpr (HAS2) v += A2[(size_t)gm * K + kc + k];
            }
            s_A[k][m] = v;
        }
        for (int i = tid; i < KC * TN / 4; i += 256) {
            int k = i / (TN / 4), nq = i % (TN / 4);
            reinterpret_cast<float4*>(&s_B[k][0])[nq] =
                reinterpret_cast<const float4*>(W + (size_t)(kc + k) * HID + n0)[nq];
        }
        __syncthreads();
#pragma unroll
        for (int k = 0; k < KC; k++) {
            float bb[4];
#pragma unroll
            for (int i = 0; i < 4; i++) bb[i] = s_B[k][cx + 32 * i];
#pragma unroll
            for (int j = 0; j < 8; j++) {
                float a = s_A[k][cy * 8 + j];
#pragma unroll
                for (int i = 0; i < 4; i++) acc[j][i] = fmaf(a, bb[i], acc[j][i]);
            }
        }
    }
#pragma unroll
    for (int j = 0; j < 8; j++) {
        int m = m0 + cy * 8 + j;
        if (m < NN) {
#pragma unroll
            for (int i = 0; i < 4; i++) {
                int n = n0 + cx + 32 * i;
                out[(size_t)m * HID + n] = fmaxf(acc[j][i] + b[n], 0.f);
            }
        }
    }
}

// ---------------- pooling ------------------------------------------------------------
__global__ void zero_out(float* out) {
    int i = blockIdx.x * 256 + threadIdx.x;
    if (i < GG * HID) out[i] = 0.f;
    if (i < GG) g_cnt[i] = 0.f;
}
__global__ void pool_count(const int* __restrict__ batch) {
    int i = blockIdx.x * 256 + threadIdx.x;
    if (i < NN) atomicAdd(&g_cnt[batch[i]], 1.f);
}
__global__ void pool_accum(const int* __restrict__ batch, float* out) {
    int c = threadIdx.x;
    int nb = blockIdx.x * 8;
#pragma unroll
    for (int j = 0; j < 8; j++) {
        int node = nb + j;
        if (node < NN) {
            int g = batch[node];
            atomicAdd(&out[g * HID + c], g_x2[(size_t)node * HID + c]);
        }
    }
}
__global__ void pool_div(float* out) {
    int i = blockIdx.x * 256 + threadIdx.x;
    if (i < GG * HID) out[i] /= fmaxf(g_cnt[i / HID], 1.f);
}

// ---------------- launch -------------------------------------------------------------
extern "C" void kernel_launch(void* const* d_in, const int* in_sizes, int n_in,
                              void* d_out, int out_size) {
    const float* x     = (const float*)d_in[0];
    const float* ea    = (const float*)d_in[1];
    const int*   eidx  = (const int*)d_in[2];   // [2, E] int32 (JAX x64 disabled)
    const int*   batch = (const int*)d_in[3];
    const float* we1 = (const float*)d_in[4];
    const float* be1 = (const float*)d_in[5];
    const float* we2 = (const float*)d_in[6];
    const float* be2 = (const float*)d_in[7];
    const float* l0_lw = (const float*)d_in[8];
    const float* l0_lb = (const float*)d_in[9];
    const float* l0_w1 = (const float*)d_in[10];
    const float* l0_b1 = (const float*)d_in[11];
    const float* l0_w2 = (const float*)d_in[12];
    const float* l0_b2 = (const float*)d_in[13];
    const float* l1_lw = (const float*)d_in[14];
    const float* l1_lb = (const float*)d_in[15];
    const float* l1_w1 = (const float*)d_in[16];
    const float* l1_b1 = (const float*)d_in[17];
    const float* l1_w2 = (const float*)d_in[18];
    const float* l1_b2 = (const float*)d_in[19];
    const int* src = eidx;
    const int* dst = eidx + EE;
    float* out = (float*)d_out;

    fuse_weights<<<HID, HID>>>(we2, be2, l0_lw, l0_lb, l1_lw, l1_lb);
    hidden_split<<<EE / 8, 256>>>(ea, we1, be1);
    zero_aggs<<<2048, 256>>>();

    // conv 0
    conv_mma<0><<<dim3(EE / 128, 1), 256>>>(src, dst, x);
    node_mlp<64, 0><<<dim3((NN + 63) / 64, 2), 256>>>(x, l0_w1, l0_b1);
    node_mlp<256, 1><<<dim3((NN + 63) / 64, 2), 256>>>(nullptr, l0_w2, l0_b2);

    // conv 1
    conv_mma<1><<<dim3(EE / 128, 2), 256>>>(src, dst, nullptr);
    node_mlp<256, 2><<<dim3((NN + 63) / 64, 2), 256>>>(nullptr, l1_w1, l1_b1);
    node_mlp<256, 3><<<dim3((NN + 63) / 64, 2), 256>>>(nullptr, l1_w2, l1_b2);

    // mean pool per graph
    zero_out<<<64, 256>>>(out);
    pool_count<<<(NN + 255) / 256, 256>>>(batch);
    pool_accum<<<(NN + 7) / 8, 256>>>(batch, out);
    pool_div<<<(GG * HID + 255) / 256, 256>>>(out);
}

// round 8
// speedup vs baseline: 1.3370x; 1.3370x over previous
#include <cuda_runtime.h>
#include <cuda_bf16.h>
#include <cstdint>

#define NN   10000
#define EE   320000
#define GG   64
#define NIN  64
#define EIN  16
#define HID  256

typedef __nv_bfloat16 bf16;

// ---------------- mma / ldmatrix helpers --------------------------------------------
__device__ __forceinline__ void ldm_x4(uint32_t addr, uint32_t& r0, uint32_t& r1,
                                       uint32_t& r2, uint32_t& r3) {
    asm volatile("ldmatrix.sync.aligned.m8n8.x4.shared.b16 {%0,%1,%2,%3}, [%4];"
                 : "=r"(r0), "=r"(r1), "=r"(r2), "=r"(r3) : "r"(addr));
}
__device__ __forceinline__ void mma_bf16(float c[4], uint32_t a0, uint32_t a1,
                                         uint32_t a2, uint32_t a3, uint32_t b0,
                                         uint32_t b1) {
    asm volatile(
        "mma.sync.aligned.m16n8k16.row.col.f32.bf16.bf16.f32 "
        "{%0,%1,%2,%3}, {%4,%5,%6,%7}, {%8,%9}, {%0,%1,%2,%3};"
        : "+f"(c[0]), "+f"(c[1]), "+f"(c[2]), "+f"(c[3])
        : "r"(a0), "r"(a1), "r"(a2), "r"(a3), "r"(b0), "r"(b1));
}
// pack (x -> low, y -> high) as bf16x2
__device__ __forceinline__ uint32_t pack_bf16x2(float x, float y) {
    uint32_t u;
    asm("cvt.rn.bf16x2.f32 %0, %1, %2;" : "=r"(u) : "f"(y), "f"(x));
    return u;
}

// ---------------- scratch (__device__ globals; no allocation allowed) ----------------
__device__ __align__(16) bf16  g_W0hT[NIN * HID], g_W0lT[NIN * HID];  // (we2@l0_lw)^T split
__device__ __align__(16) bf16  g_W1hT[HID * HID], g_W1lT[HID * HID];  // (we2@l1_lw)^T split
__device__ __align__(16) float g_b0f[NIN];
__device__ __align__(16) float g_b1f[HID];
__device__ __align__(16) float g_agg0[NN * NIN];
__device__ __align__(16) float g_agg1[NN * HID];
__device__ __align__(16) float g_x1[NN * HID];
__device__ __align__(16) float g_tmp[NN * HID];
__device__ __align__(16) float g_x2[NN * HID];
__device__ float g_cnt[GG];

// ---------------- weight pre-products -> transposed bf16 split -----------------------
__global__ void fuse_weights(const float* __restrict__ we2, const float* __restrict__ be2,
                             const float* __restrict__ l0_lw, const float* __restrict__ l0_lb,
                             const float* __restrict__ l1_lw, const float* __restrict__ l1_lb) {
    __shared__ float s_w[HID];
    int k = blockIdx.x;      // hidden row of we2
    int n = threadIdx.x;     // output col
    s_w[n] = we2[k * HID + n];
    __syncthreads();
    float acc = 0.f;
    for (int j = 0; j < HID; j++) acc += s_w[j] * l1_lw[j * HID + n];
    bf16 h1 = __float2bfloat16_rn(acc);
    g_W1hT[(size_t)n * HID + k] = h1;
    g_W1lT[(size_t)n * HID + k] = __float2bfloat16_rn(acc - __bfloat162float(h1));
    if (n < NIN) {
        float a0 = 0.f;
        for (int j = 0; j < HID; j++) a0 += s_w[j] * l0_lw[j * NIN + n];
        bf16 h0 = __float2bfloat16_rn(a0);
        g_W0hT[(size_t)n * HID + k] = h0;
        g_W0lT[(size_t)n * HID + k] = __float2bfloat16_rn(a0 - __bfloat162float(h0));
    }
    if (k == 0) {
        float bb = 0.f;
        for (int j = 0; j < HID; j++) bb += be2[j] * l1_lw[j * HID + n];
        g_b1f[n] = bb + l1_lb[n];
        if (n < NIN) {
            float b0 = 0.f;
            for (int j = 0; j < HID; j++) b0 += be2[j] * l0_lw[j * NIN + n];
            g_b0f[n] = b0 + l0_lb[n];
        }
    }
}

__global__ void zero_aggs() {
    int i = blockIdx.x * 256 + threadIdx.x;
    int st = gridDim.x * 256;
    for (int j = i; j < NN * HID; j += st) g_agg1[j] = 0.f;
    for (int j = i; j < NN * NIN; j += st) g_agg0[j] = 0.f;
}

// ---------------- fused edge conv: bf16x3 mma, hidden recomputed per chunk -----------
// TE=64 edges/block, K=256 in KC=16 chunks. Per chunk: recompute hidden slice
// relu(ea@we1+be1)[:,kc:kc+16] in fp32, split to bf16 hi/lo in smem; weight chunk
// (pre-split, n-major) loaded to smem; m16n8k16 mma with 3-term split. Epilogue:
// msg = relu(x[src]+eproj+bias) -> atomicAdd agg[dst].
template <int CONV>
__global__ void __launch_bounds__(256) conv_bf16(const int* __restrict__ src,
                                                 const int* __restrict__ dst,
                                                 const float* __restrict__ we1,
                                                 const float* __restrict__ be1,
                                                 const float* __restrict__ xin_param) {
    constexpr int CIN = CONV ? HID : NIN;
    constexpr int TN  = CIN;           // full output width in one pass
    constexpr int TE  = 64, KC = 16;
    constexpr int NFW = TN / 32;       // n8 frags per warp (8 warps: 2e x 4n)
    const bf16* WhT = CONV ? g_W1hT : g_W0hT;
    const bf16* WlT = CONV ? g_W1lT : g_W0lT;
    const float* bf = CONV ? g_b1f : g_b0f;
    const float* xp = CONV ? g_x1 : xin_param;
    float* agg      = CONV ? g_agg1 : g_agg0;

    __shared__ __align__(16) float s_ea[TE][17];     // edge_attr tile (pad 17: conflict-free)
    __shared__ __align__(16) float s_w1c[EIN][KC];   // we1 chunk
    __shared__ __align__(16) bf16 sAh[TE][24], sAl[TE][24];   // hidden chunk split (48B rows)
    __shared__ __align__(16) bf16 sBh[TN][24], sBl[TN][24];   // weight chunk split (n-major)
    __shared__ int s_src[TE], s_dst[TE];

    const int tid = threadIdx.x;
    const int lane = tid & 31, w = tid >> 5;
    const int g = lane >> 2, t4 = lane & 3;
    const int we = (w >> 2) * 32;           // warp edge base (0 / 32)
    const int wn = (w & 3) * (TN / 4);      // warp n base
    const int e0 = blockIdx.x * TE;

    // one-time loads
    if (tid < TE) {
        s_src[tid] = src[e0 + tid];
        s_dst[tid] = dst[e0 + tid];
    }
    {   // ea tile: 64 x 16 floats
        int e = tid >> 2, i4 = (tid & 3) * 4;
        float4 v = *reinterpret_cast<const float4*>(
            // ea pointer passed via we1? no — pass ea separately below
            (const float*)nullptr);
        (void)v; (void)e; (void)i4;
    }
    // (ea loaded in loop below; placeholder removed)

    float acc[2][NFW][4];
#pragma unroll
    for (int ti = 0; ti < 2; ti++)
#pragma unroll
        for (int f = 0; f < NFW; f++)
#pragma unroll
            for (int c = 0; c < 4; c++) acc[ti][f][c] = 0.f;

    const uint32_t sAh_b = (uint32_t)__cvta_generic_to_shared(&sAh[0][0]);
    const uint32_t sAl_b = (uint32_t)__cvta_generic_to_shared(&sAl[0][0]);
    const uint32_t sBh_b = (uint32_t)__cvta_generic_to_shared(&sBh[0][0]);
    const uint32_t sBl_b = (uint32_t)__cvta_generic_to_shared(&sBl[0][0]);

    // hidden-compute thread mapping
    const int he = tid & 63, hq = (tid >> 6) * 4;

    for (int kc = 0; kc < HID; kc += KC) {
        __syncthreads();   // consumers of previous chunk done
        // load we1 chunk [16][16]
        if (tid < 64) {
            int i = tid >> 2, c = (tid & 3) * 4;
            float4 v = *reinterpret_cast<const float4*>(we1 + i * HID + kc + c);
            s_w1c[i][c] = v.x; s_w1c[i][c + 1] = v.y;
            s_w1c[i][c + 2] = v.z; s_w1c[i][c + 3] = v.w;
        }
        // load B chunk split (n-major, 16 bf16 = 32B per row) -> sBh/sBl
        for (int idx = tid; idx < TN * 4; idx += 256) {
            int n = idx >> 2, q = idx & 3;
            const uint4* gsrc = (q < 2)
                ? reinterpret_cast<const uint4*>(WhT + (size_t)n * HID + kc) + (q & 1)
                : reinterpret_cast<const uint4*>(WlT + (size_t)n * HID + kc) + (q & 1);
            bf16* sdst = (q < 2) ? &sBh[n][(q & 1) * 8] : &sBl[n][(q & 1) * 8];
            *reinterpret_cast<uint4*>(sdst) = *gsrc;
        }
        __syncthreads();   // s_w1c ready
        // hidden: thread computes 4 k-values for edge he
        {
            float4 v = *reinterpret_cast<const float4*>(be1 + kc + hq);
#pragma unroll
            for (int i = 0; i < EIN; i++) {
                float a = s_ea[he][i];
                v.x = fmaf(a, s_w1c[i][hq],     v.x);
                v.y = fmaf(a, s_w1c[i][hq + 1], v.y);
                v.z = fmaf(a, s_w1c[i][hq + 2], v.z);
                v.w = fmaf(a, s_w1c[i][hq + 3], v.w);
            }
            v.x = fmaxf(v.x, 0.f); v.y = fmaxf(v.y, 0.f);
            v.z = fmaxf(v.z, 0.f); v.w = fmaxf(v.w, 0.f);
            uint32_t h01 = pack_bf16x2(v.x, v.y);
            uint32_t h23 = pack_bf16x2(v.z, v.w);
            float hx = __uint_as_float(h01 << 16), hy = __uint_as_float(h01 & 0xffff0000u);
            float hz = __uint_as_float(h23 << 16), hw = __uint_as_float(h23 & 0xffff0000u);
            uint32_t l01 = pack_bf16x2(v.x - hx, v.y - hy);
            uint32_t l23 = pack_bf16x2(v.z - hz, v.w - hw);
            uint2* ph = reinterpret_cast<uint2*>(reinterpret_cast<char*>(&sAh[0][0]) +
                                                 he * 48 + hq * 2);
            uint2* pl = reinterpret_cast<uint2*>(reinterpret_cast<char*>(&sAl[0][0]) +
                                                 he * 48 + hq * 2);
            *ph = make_uint2(h01, h23);
            *pl = make_uint2(l01, l23);
        }
        __syncthreads();   // sA / sB ready
        // mma
        uint32_t AH[2][4], AL[2][4];
        {
            uint32_t roff = (uint32_t)(lane & 15) * 48 + (uint32_t)(lane >> 4) * 16;
#pragma unroll
            for (int ti = 0; ti < 2; ti++) {
                uint32_t ra = (uint32_t)(we + ti * 16) * 48 + roff;
                ldm_x4(sAh_b + ra, AH[ti][0], AH[ti][1], AH[ti][2], AH[ti][3]);
                ldm_x4(sAl_b + ra, AL[ti][0], AL[ti][1], AL[ti][2], AL[ti][3]);
            }
#pragma unroll
            for (int nfp = 0; nfp < NFW / 2; nfp++) {
                uint32_t rb = (uint32_t)(wn + nfp * 16) * 48 + roff;
                uint32_t bh0, bh1, bh2, bh3, bl0, bl1, bl2, bl3;
                ldm_x4(sBh_b + rb, bh0, bh1, bh2, bh3);
                ldm_x4(sBl_b + rb, bl0, bl1, bl2, bl3);
#pragma unroll
                for (int ti = 0; ti < 2; ti++) {
                    float* c0 = acc[ti][2 * nfp];
                    float* c1 = acc[ti][2 * nfp + 1];
                    mma_bf16(c0, AH[ti][0], AH[ti][1], AH[ti][2], AH[ti][3], bh0, bh2);
                    mma_bf16(c0, AH[ti][0], AH[ti][1], AH[ti][2], AH[ti][3], bl0, bl2);
                    mma_bf16(c0, AL[ti][0], AL[ti][1], AL[ti][2], AL[ti][3], bh0, bh2);
                    mma_bf16(c1, AH[ti][0], AH[ti][1], AH[ti][2], AH[ti][3], bh1, bh3);
                    mma_bf16(c1, AH[ti][0], AH[ti][1], AH[ti][2], AH[ti][3], bl1, bl3);
                    mma_bf16(c1, AL[ti][0], AL[ti][1], AL[ti][2], AL[ti][3], bh1, bh3);
                }
            }
        }
    }

    // epilogue
#pragma unroll
    for (int ti = 0; ti < 2; ti++) {
        int er0 = we + ti * 16 + g, er1 = er0 + 8;
        int s0 = s_src[er0], d0 = s_dst[er0];
        int s1 = s_src[er1], d1 = s_dst[er1];
#pragma unroll
        for (int f = 0; f < NFW; f++) {
            int nc = wn + (f >> 1) * 16 + (f & 1) * 8 + 2 * t4;
            float b0v = bf[nc], b1v = bf[nc + 1];
            float2 x0 = *reinterpret_cast<const float2*>(xp + (size_t)s0 * CIN + nc);
            float2 x1 = *reinterpret_cast<const float2*>(xp + (size_t)s1 * CIN + nc);
            float* a0p = agg + (size_t)d0 * CIN + nc;
            float* a1p = agg + (size_t)d1 * CIN + nc;
            atomicAdd(a0p,     fmaxf(acc[ti][f][0] + b0v + x0.x, 0.f));
            atomicAdd(a0p + 1, fmaxf(acc[ti][f][1] + b1v + x0.y, 0.f));
            atomicAdd(a1p,     fmaxf(acc[ti][f][2] + b0v + x1.x, 0.f));
            atomicAdd(a1p + 1, fmaxf(acc[ti][f][3] + b1v + x1.y, 0.f));
        }
    }
}

// ea tile loader shares the conv kernel; declared as separate pre-pass into smem is not
// possible across kernels, so conv_bf16 needs ea: fix by passing ea and loading at top.
// (The template above references s_ea; the loader below is spliced via macro.)
// -- We implement the load directly here by re-declaring conv with ea param: see launch.

// Load of s_ea happens at kernel start; to keep one definition, conv_bf16 is wrapped:
template <int CONV>
__global__ void __launch_bounds__(256) conv_bf16_ea(const float* __restrict__ ea,
                                                    const int* __restrict__ src,
                                                    const int* __restrict__ dst,
                                                    const float* __restrict__ we1,
                                                    const float* __restrict__ be1,
                                                    const float* __restrict__ xin_param);

// Full implementation with ea load (the version actually launched).
template <int CONV>
__global__ void __launch_bounds__(256) conv_bf16_ea(const float* __restrict__ ea,
                                                    const int* __restrict__ src,
                                                    const int* __restrict__ dst,
                                                    const float* __restrict__ we1,
                                                    const float* __restrict__ be1,
                                                    const float* __restrict__ xin_param) {
    constexpr int CIN = CONV ? HID : NIN;
    constexpr int TN  = CIN;
    constexpr int TE  = 64, KC = 16;
    constexpr int NFW = TN / 32;
    const bf16* WhT = CONV ? g_W1hT : g_W0hT;
    const bf16* WlT = CONV ? g_W1lT : g_W0lT;
    const float* bf = CONV ? g_b1f : g_b0f;
    const float* xp = CONV ? g_x1 : xin_param;
    float* agg      = CONV ? g_agg1 : g_agg0;

    __shared__ __align__(16) float s_ea[TE][17];
    __shared__ __align__(16) float s_w1c[EIN][KC];
    __shared__ __align__(16) bf16 sAh[TE][24], sAl[TE][24];
    __shared__ __align__(16) bf16 sBh[TN][24], sBl[TN][24];
    __shared__ int s_src[TE], s_dst[TE];

    const int tid = threadIdx.x;
    const int lane = tid & 31, w = tid >> 5;
    const int g = lane >> 2, t4 = lane & 3;
    const int we = (w >> 2) * 32;
    const int wn = (w & 3) * (TN / 4);
    const int e0 = blockIdx.x * TE;

    if (tid < TE) {
        s_src[tid] = src[e0 + tid];
        s_dst[tid] = dst[e0 + tid];
    }
    {
        int e = tid >> 2, i4 = (tid & 3) * 4;
        float4 v = *reinterpret_cast<const float4*>(ea + (size_t)(e0 + e) * EIN + i4);
        s_ea[e][i4] = v.x; s_ea[e][i4 + 1] = v.y;
        s_ea[e][i4 + 2] = v.z; s_ea[e][i4 + 3] = v.w;
    }

    float acc[2][NFW][4];
#pragma unroll
    for (int ti = 0; ti < 2; ti++)
#pragma unroll
        for (int f = 0; f < NFW; f++)
#pragma unroll
            for (int c = 0; c < 4; c++) acc[ti][f][c] = 0.f;

    const uint32_t sAh_b = (uint32_t)__cvta_generic_to_shared(&sAh[0][0]);
    const uint32_t sAl_b = (uint32_t)__cvta_generic_to_shared(&sAl[0][0]);
    const uint32_t sBh_b = (uint32_t)__cvta_generic_to_shared(&sBh[0][0]);
    const uint32_t sBl_b = (uint32_t)__cvta_generic_to_shared(&sBl[0][0]);
    const int he = tid & 63, hq = (tid >> 6) * 4;

    for (int kc = 0; kc < HID; kc += KC) {
        __syncthreads();
        if (tid < 64) {
            int i = tid >> 2, c = (tid & 3) * 4;
            float4 v = *reinterpret_cast<const float4*>(we1 + i * HID + kc + c);
            s_w1c[i][c] = v.x; s_w1c[i][c + 1] = v.y;
            s_w1c[i][c + 2] = v.z; s_w1c[i][c + 3] = v.w;
        }
        for (int idx = tid; idx < TN * 4; idx += 256) {
            int n = idx >> 2, q = idx & 3;
            const uint4* gsrc = (q < 2)
                ? reinterpret_cast<const uint4*>(WhT + (size_t)n * HID + kc) + (q & 1)
                : reinterpret_cast<const uint4*>(WlT + (size_t)n * HID + kc) + (q & 1);
            bf16* sdst = (q < 2) ? &sBh[n][(q & 1) * 8] : &sBl[n][(q & 1) * 8];
            *reinterpret_cast<uint4*>(sdst) = *gsrc;
        }
        __syncthreads();
        {
            float4 v = *reinterpret_cast<const float4*>(be1 + kc + hq);
#pragma unroll
            for (int i = 0; i < EIN; i++) {
                float a = s_ea[he][i];
                v.x = fmaf(a, s_w1c[i][hq],     v.x);
                v.y = fmaf(a, s_w1c[i][hq + 1], v.y);
                v.z = fmaf(a, s_w1c[i][hq + 2], v.z);
                v.w = fmaf(a, s_w1c[i][hq + 3], v.w);
            }
            v.x = fmaxf(v.x, 0.f); v.y = fmaxf(v.y, 0.f);
            v.z = fmaxf(v.z, 0.f); v.w = fmaxf(v.w, 0.f);
            uint32_t h01 = pack_bf16x2(v.x, v.y);
            uint32_t h23 = pack_bf16x2(v.z, v.w);
            float hx = __uint_as_float(h01 << 16), hy = __uint_as_float(h01 & 0xffff0000u);
            float hz = __uint_as_float(h23 << 16), hw = __uint_as_float(h23 & 0xffff0000u);
            uint32_t l01 = pack_bf16x2(v.x - hx, v.y - hy);
            uint32_t l23 = pack_bf16x2(v.z - hz, v.w - hw);
            *reinterpret_cast<uint2*>(reinterpret_cast<char*>(&sAh[0][0]) + he * 48 + hq * 2) =
                make_uint2(h01, h23);
            *reinterpret_cast<uint2*>(reinterpret_cast<char*>(&sAl[0][0]) + he * 48 + hq * 2) =
                make_uint2(l01, l23);
        }
        __syncthreads();
        uint32_t AH[2][4], AL[2][4];
        uint32_t roff = (uint32_t)(lane & 15) * 48 + (uint32_t)(lane >> 4) * 16;
#pragma unroll
        for (int ti = 0; ti < 2; ti++) {
            uint32_t ra = (uint32_t)(we + ti * 16) * 48 + roff;
            ldm_x4(sAh_b + ra, AH[ti][0], AH[ti][1], AH[ti][2], AH[ti][3]);
            ldm_x4(sAl_b + ra, AL[ti][0], AL[ti][1], AL[ti][2], AL[ti][3]);
        }
#pragma unroll
        for (int nfp = 0; nfp < NFW / 2; nfp++) {
            uint32_t rb = (uint32_t)(wn + nfp * 16) * 48 + roff;
            uint32_t bh0, bh1, bh2, bh3, bl0, bl1, bl2, bl3;
            ldm_x4(sBh_b + rb, bh0, bh1, bh2, bh3);
            ldm_x4(sBl_b + rb, bl0, bl1, bl2, bl3);
#pragma unroll
            for (int ti = 0; ti < 2; ti++) {
                float* c0 = acc[ti][2 * nfp];
                float* c1 = acc[ti][2 * nfp + 1];
                mma_bf16(c0, AH[ti][0], AH[ti][1], AH[ti][2], AH[ti][3], bh0, bh2);
                mma_bf16(c0, AH[ti][0], AH[ti][1], AH[ti][2], AH[ti][3], bl0, bl2);
                mma_bf16(c0, AL[ti][0], AL[ti][1], AL[ti][2], AL[ti][3], bh0, bh2);
                mma_bf16(c1, AH[ti][0], AH[ti][1], AH[ti][2], AH[ti][3], bh1, bh3);
                mma_bf16(c1, AH[ti][0], AH[ti][1], AH[ti][2], AH[ti][3], bl1, bl3);
                mma_bf16(c1, AL[ti][0], AL[ti][1], AL[ti][2], AL[ti][3], bh1, bh3);
            }
        }
    }

#pragma unroll
    for (int ti = 0; ti < 2; ti++) {
        int er0 = we + ti * 16 + g, er1 = er0 + 8;
        int s0 = s_src[er0], d0 = s_dst[er0];
        int s1 = s_src[er1], d1 = s_dst[er1];
#pragma unroll
        for (int f = 0; f < NFW; f++) {
            int nc = wn + (f >> 1) * 16 + (f & 1) * 8 + 2 * t4;
            float b0v = bf[nc], b1v = bf[nc + 1];
            float2 x0 = *reinterpret_cast<const float2*>(xp + (size_t)s0 * CIN + nc);
            float2 x1 = *reinterpret_cast<const float2*>(xp + (size_t)s1 * CIN + nc);
            float* a0p = agg + (size_t)d0 * CIN + nc;
            float* a1p = agg + (size_t)d1 * CIN + nc;
            atomicAdd(a0p,     fmaxf(acc[ti][f][0] + b0v + x0.x, 0.f));
            atomicAdd(a0p + 1, fmaxf(acc[ti][f][1] + b1v + x0.y, 0.f));
            atomicAdd(a1p,     fmaxf(acc[ti][f][2] + b0v + x1.x, 0.f));
            atomicAdd(a1p + 1, fmaxf(acc[ti][f][3] + b1v + x1.y, 0.f));
        }
    }
}

// ---------------- node MLP GEMM (fp32, proven) ---------------------------------------
template <int K, int SEL>
__global__ void __launch_bounds__(256) node_mlp(const float* __restrict__ xin_param,
                                                const float* __restrict__ W,
                                                const float* __restrict__ b) {
    constexpr int TM = 64, TN = 128, KC = 32;
    constexpr bool HAS2 = (SEL == 0 || SEL == 2);
    const float* A1 = (SEL == 0) ? xin_param : (SEL == 2 ? g_x1 : g_tmp);
    const float* A2 = (SEL == 0) ? g_agg0 : g_agg1;
    float* out = (SEL == 0 || SEL == 2) ? g_tmp : (SEL == 1 ? g_x1 : g_x2);

    __shared__ float s_A[KC][TM + 1];
    __shared__ __align__(16) float s_B[KC][TN];
    int tid = threadIdx.x, cx = tid & 31, cy = tid >> 5;
    int m0 = blockIdx.x * TM, n0 = blockIdx.y * TN;
    float acc[8][4] = {};

    for (int kc = 0; kc < K; kc += KC) {
        __syncthreads();
        for (int i = tid; i < KC * TM; i += 256) {
            int k = i % KC, m = i / KC, gm = m0 + m;
            float v = 0.f;
            if (gm < NN) {
                v = A1[(size_t)gm * K + kc + k];
                if constexpr (HAS2) v += A2[(size_t)gm * K + kc + k];
            }
            s_A[k][m] = v;
        }
        for (int i = tid; i < KC * TN / 4; i += 256) {
            int k = i / (TN / 4), nq = i % (TN / 4);
            reinterpret_cast<float4*>(&s_B[k][0])[nq] =
                reinterpret_cast<const float4*>(W + (size_t)(kc + k) * HID + n0)[nq];
        }
        __syncthreads();
#pragma unroll
        for (int k = 0; k < KC; k++) {
            float bb[4];
#pragma unroll
            for (int i = 0; i < 4; i++) bb[i] = s_B[k][cx + 32 * i];
#pragma unroll
            for (int j = 0; j < 8; j++) {
                float a = s_A[k][cy * 8 + j];
#pragma unroll
                for (int i = 0; i < 4; i++) acc[j][i] = fmaf(a, bb[i], acc[j][i]);
            }
        }
    }
#pragma unroll
    for (int j = 0; j < 8; j++) {
        int m = m0 + cy * 8 + j;
        if (m < NN) {
#pragma unroll
            for (int i = 0; i < 4; i++) {
                int n = n0 + cx + 32 * i;
                out[(size_t)m * HID + n] = fmaxf(acc[j][i] + b[n], 0.f);
            }
        }
    }
}

// ---------------- pooling ------------------------------------------------------------
__global__ void zero_out(float* out) {
    int i = blockIdx.x * 256 + threadIdx.x;
    if (i < GG * HID) out[i] = 0.f;
    if (i < GG) g_cnt[i] = 0.f;
}
__global__ void pool_count(const int* __restrict__ batch) {
    int i = blockIdx.x * 256 + threadIdx.x;
    if (i < NN) atomicAdd(&g_cnt[batch[i]], 1.f);
}
__global__ void pool_accum(const int* __restrict__ batch, float* out) {
    int c = threadIdx.x;
    int nb = blockIdx.x * 8;
#pragma unroll
    for (int j = 0; j < 8; j++) {
        int node = nb + j;
        if (node < NN) {
            int g = batch[node];
            atomicAdd(&out[g * HID + c], g_x2[(size_t)node * HID + c]);
        }
    }
}
__global__ void pool_div(float* out) {
    int i = blockIdx.x * 256 + threadIdx.x;
    if (i < GG * HID) out[i] /= fmaxf(g_cnt[i / HID], 1.f);
}

// ---------------- launch -------------------------------------------------------------
extern "C" void kernel_launch(void* const* d_in, const int* in_sizes, int n_in,
                              void* d_out, int out_size) {
    const float* x     = (const float*)d_in[0];
    const float* ea    = (const float*)d_in[1];
    const int*   eidx  = (const int*)d_in[2];   // [2, E] int32 (JAX x64 disabled)
    const int*   batch = (const int*)d_in[3];
    const float* we1 = (const float*)d_in[4];
    const float* be1 = (const float*)d_in[5];
    const float* we2 = (const float*)d_in[6];
    const float* be2 = (const float*)d_in[7];
    const float* l0_lw = (const float*)d_in[8];
    const float* l0_lb = (const float*)d_in[9];
    const float* l0_w1 = (const float*)d_in[10];
    const float* l0_b1 = (const float*)d_in[11];
    const float* l0_w2 = (const float*)d_in[12];
    const float* l0_b2 = (const float*)d_in[13];
    const float* l1_lw = (const float*)d_in[14];
    const float* l1_lb = (const float*)d_in[15];
    const float* l1_w1 = (const float*)d_in[16];
    const float* l1_b1 = (const float*)d_in[17];
    const float* l1_w2 = (const float*)d_in[18];
    const float* l1_b2 = (const float*)d_in[19];
    const int* src = eidx;
    const int* dst = eidx + EE;
    float* out = (float*)d_out;

    fuse_weights<<<HID, HID>>>(we2, be2, l0_lw, l0_lb, l1_lw, l1_lb);
    zero_aggs<<<2048, 256>>>();

    // conv 0
    conv_bf16_ea<0><<<EE / 64, 256>>>(ea, src, dst, we1, be1, x);
    node_mlp<64, 0><<<dim3((NN + 63) / 64, 2), 256>>>(x, l0_w1, l0_b1);
    node_mlp<256, 1><<<dim3((NN + 63) / 64, 2), 256>>>(nullptr, l0_w2, l0_b2);

    // conv 1
    conv_bf16_ea<1><<<EE / 64, 256>>>(ea, src, dst, we1, be1, nullptr);
    node_mlp<256, 2><<<dim3((NN + 63) / 64, 2), 256>>>(nullptr, l1_w1, l1_b1);
    node_mlp<256, 3><<<dim3((NN + 63) / 64, 2), 256>>>(nullptr, l1_w2, l1_b2);

    // mean pool per graph
    zero_out<<<64, 256>>>(out);
    pool_count<<<(NN + 255) / 256, 256>>>(batch);
    pool_accum<<<(NN + 7) / 8, 256>>>(batch, out);
    pool_div<<<(GG * HID + 255) / 256, 256>>>(out);
}

// round 9
// speedup vs baseline: 1.5992x; 1.1961x over previous
#include <cuda_runtime.h>
#include <cuda_bf16.h>
#include <cstdint>

#define NN   10000
#define EE   320000
#define GG   64
#define NIN  64
#define EIN  16
#define HID  256

typedef __nv_bfloat16 bf16;

// ---------------- mma / ldmatrix helpers --------------------------------------------
__device__ __forceinline__ void ldm_x4(uint32_t addr, uint32_t& r0, uint32_t& r1,
                                       uint32_t& r2, uint32_t& r3) {
    asm volatile("ldmatrix.sync.aligned.m8n8.x4.shared.b16 {%0,%1,%2,%3}, [%4];"
                 : "=r"(r0), "=r"(r1), "=r"(r2), "=r"(r3) : "r"(addr));
}
__device__ __forceinline__ void mma_bf16(float c[4], uint32_t a0, uint32_t a1,
                                         uint32_t a2, uint32_t a3, uint32_t b0,
                                         uint32_t b1) {
    asm volatile(
        "mma.sync.aligned.m16n8k16.row.col.f32.bf16.bf16.f32 "
        "{%0,%1,%2,%3}, {%4,%5,%6,%7}, {%8,%9}, {%0,%1,%2,%3};"
        : "+f"(c[0]), "+f"(c[1]), "+f"(c[2]), "+f"(c[3])
        : "r"(a0), "r"(a1), "r"(a2), "r"(a3), "r"(b0), "r"(b1));
}
// pack (x -> low half, y -> high half) as bf16x2
__device__ __forceinline__ uint32_t pack_bf16x2(float x, float y) {
    uint32_t u;
    asm("cvt.rn.bf16x2.f32 %0, %1, %2;" : "=r"(u) : "f"(y), "f"(x));
    return u;
}
__device__ __forceinline__ float bflo(uint32_t u) { return __uint_as_float(u << 16); }
__device__ __forceinline__ float bfhi(uint32_t u) { return __uint_as_float(u & 0xffff0000u); }

// ---------------- scratch (__device__ globals; no allocation allowed) ----------------
__device__ __align__(16) bf16  g_W0hT[NIN * HID], g_W0lT[NIN * HID];  // (we2@l0_lw)^T split
__device__ __align__(16) bf16  g_W1hT[HID * HID], g_W1lT[HID * HID];  // (we2@l1_lw)^T split
__device__ __align__(16) bf16  g_we1hT[HID * EIN], g_we1lT[HID * EIN];  // we1^T split [n][k]
__device__ __align__(16) float g_b0f[NIN];
__device__ __align__(16) float g_b1f[HID];
__device__ __align__(16) float g_agg0[NN * NIN];
__device__ __align__(16) float g_agg1[NN * HID];
__device__ __align__(16) float g_x1[NN * HID];
__device__ __align__(16) float g_tmp[NN * HID];
__device__ __align__(16) float g_x2[NN * HID];
__device__ float g_cnt[GG];

// ---------------- weight pre-products -> transposed bf16 splits ----------------------
__global__ void fuse_weights(const float* __restrict__ we1,
                             const float* __restrict__ we2, const float* __restrict__ be2,
                             const float* __restrict__ l0_lw, const float* __restrict__ l0_lb,
                             const float* __restrict__ l1_lw, const float* __restrict__ l1_lb) {
    __shared__ float s_w[HID];
    int k = blockIdx.x;      // hidden row of we2
    int n = threadIdx.x;     // output col
    s_w[n] = we2[k * HID + n];
    __syncthreads();
    float acc = 0.f;
    for (int j = 0; j < HID; j++) acc += s_w[j] * l1_lw[j * HID + n];
    bf16 h1 = __float2bfloat16_rn(acc);
    g_W1hT[(size_t)n * HID + k] = h1;
    g_W1lT[(size_t)n * HID + k] = __float2bfloat16_rn(acc - __bfloat162float(h1));
    if (n < NIN) {
        float a0 = 0.f;
        for (int j = 0; j < HID; j++) a0 += s_w[j] * l0_lw[j * NIN + n];
        bf16 h0 = __float2bfloat16_rn(a0);
        g_W0hT[(size_t)n * HID + k] = h0;
        g_W0lT[(size_t)n * HID + k] = __float2bfloat16_rn(a0 - __bfloat162float(h0));
    }
    if (k < EIN) {   // we1 split, n-major [n][k]
        float v = we1[k * HID + n];
        bf16 hh = __float2bfloat16_rn(v);
        g_we1hT[(size_t)n * EIN + k] = hh;
        g_we1lT[(size_t)n * EIN + k] = __float2bfloat16_rn(v - __bfloat162float(hh));
    }
    if (k == 0) {
        float bb = 0.f;
        for (int j = 0; j < HID; j++) bb += be2[j] * l1_lw[j * HID + n];
        g_b1f[n] = bb + l1_lb[n];
        if (n < NIN) {
            float b0 = 0.f;
            for (int j = 0; j < HID; j++) b0 += be2[j] * l0_lw[j * NIN + n];
            g_b0f[n] = b0 + l0_lb[n];
        }
    }
}

__global__ void zero_aggs() {
    int i = blockIdx.x * 256 + threadIdx.x;
    int st = gridDim.x * 256;
    for (int j = i; j < NN * HID; j += st) g_agg1[j] = 0.f;
    for (int j = i; j < NN * NIN; j += st) g_agg0[j] = 0.f;
}

// ---------------- smem layout for conv kernel (dynamic) ------------------------------
// sAh [64][264] bf16  (rows 528B, 16B-mult)          0      .. 33792
// sAl [64][264] bf16                                  33792  .. 67584
// sBh [256][24] bf16  (rows 48B)                      67584  .. 79872
// sBl [256][24] bf16                                  79872  .. 92160
// s_ea [64][20] f32   (rows 80B)                      92160  .. 97280
// s_b1 [256] f32                                      97280  .. 98304
// s_src[64], s_dst[64] int                            98304  .. 98816
#define OFF_AH  0
#define OFF_AL  33792
#define OFF_BH  67584
#define OFF_BL  79872
#define OFF_EA  92160
#define OFF_B1  97280
#define OFF_SRC 98304
#define OFF_DST 98560
#define CONV_SMEM 98816

// ---------------- fused edge conv: all-tensor-core -----------------------------------
// Phase 1: H[64x256] = relu(ea@we1 + be1) via bf16x3 mma, split hi/lo into sAh/sAl.
// Phase 2: e_proj = H @ Wf (bf16x3, KC=16 chunks of pre-split n-major weights).
// Epilogue: msg = relu(x[src] + e_proj + bias) -> atomicAdd agg[dst].
template <int CONV>
__global__ void __launch_bounds__(256, 2) conv_tc(const float* __restrict__ ea,
                                                  const int* __restrict__ src,
                                                  const int* __restrict__ dst,
                                                  const float* __restrict__ be1,
                                                  const float* __restrict__ xin_param) {
    constexpr int CIN = CONV ? HID : NIN;
    constexpr int TN  = CIN;
    constexpr int NFW = TN / 32;       // n8 frags per warp in phase 2
    extern __shared__ __align__(16) char sm[];
    const bf16* WhT = CONV ? g_W1hT : g_W0hT;
    const bf16* WlT = CONV ? g_W1lT : g_W0lT;
    const float* bfb = CONV ? g_b1f : g_b0f;
    const float* xp  = CONV ? g_x1 : xin_param;
    float* agg       = CONV ? g_agg1 : g_agg0;

    float (*s_ea)[20] = reinterpret_cast<float(*)[20]>(sm + OFF_EA);
    float* s_b1 = reinterpret_cast<float*>(sm + OFF_B1);
    int* s_src = reinterpret_cast<int*>(sm + OFF_SRC);
    int* s_dst = reinterpret_cast<int*>(sm + OFF_DST);

    const int tid = threadIdx.x;
    const int lane = tid & 31, w = tid >> 5;
    const int g = lane >> 2, t4 = lane & 3;
    const int e0 = blockIdx.x * 64;

    // one-time loads
    if (tid < 64) {
        s_src[tid] = src[e0 + tid];
        s_dst[tid] = dst[e0 + tid];
    }
    {
        int e = tid >> 2, q = (tid & 3) * 4;
        float4 v = *reinterpret_cast<const float4*>(ea + (size_t)(e0 + e) * EIN + q);
        s_ea[e][q] = v.x; s_ea[e][q + 1] = v.y; s_ea[e][q + 2] = v.z; s_ea[e][q + 3] = v.w;
    }
    s_b1[tid] = be1[tid];
    // we1^T split tiles into sB buffers (256 rows x 16 bf16 = 2x16B per row)
    for (int i = tid; i < 512; i += 256) {
        int n = i >> 1, h = i & 1;
        *reinterpret_cast<uint4*>(sm + OFF_BH + n * 48 + h * 16) =
            *reinterpret_cast<const uint4*>(g_we1hT + (size_t)n * EIN + h * 8);
        *reinterpret_cast<uint4*>(sm + OFF_BL + n * 48 + h * 16) =
            *reinterpret_cast<const uint4*>(g_we1lT + (size_t)n * EIN + h * 8);
    }
    __syncthreads();

    const uint32_t sAh_b = (uint32_t)__cvta_generic_to_shared(sm + OFF_AH);
    const uint32_t sAl_b = (uint32_t)__cvta_generic_to_shared(sm + OFF_AL);
    const uint32_t sBh_b = (uint32_t)__cvta_generic_to_shared(sm + OFF_BH);
    const uint32_t sBl_b = (uint32_t)__cvta_generic_to_shared(sm + OFF_BL);
    const uint32_t roffB = (uint32_t)(lane & 15) * 48 + (uint32_t)(lane >> 4) * 16;
    const uint32_t roffA = (uint32_t)(lane & 15) * 528 + (uint32_t)(lane >> 4) * 16;

    // ---- phase 1: hidden tile via mma ----
    {
        const int wr = w >> 1, wh = w & 1;      // row-tile 0..3, col half 0..1
        const int r0 = wr * 16 + g, r1 = r0 + 8;
        // A frags (ea) hi/lo, k=16
        float v00 = s_ea[r0][2 * t4],     v01 = s_ea[r0][2 * t4 + 1];
        float v10 = s_ea[r1][2 * t4],     v11 = s_ea[r1][2 * t4 + 1];
        float v02 = s_ea[r0][8 + 2 * t4], v03 = s_ea[r0][9 + 2 * t4];
        float v12 = s_ea[r1][8 + 2 * t4], v13 = s_ea[r1][9 + 2 * t4];
        uint32_t ah0 = pack_bf16x2(v00, v01), ah1 = pack_bf16x2(v10, v11);
        uint32_t ah2 = pack_bf16x2(v02, v03), ah3 = pack_bf16x2(v12, v13);
        uint32_t al0 = pack_bf16x2(v00 - bflo(ah0), v01 - bfhi(ah0));
        uint32_t al1 = pack_bf16x2(v10 - bflo(ah1), v11 - bfhi(ah1));
        uint32_t al2 = pack_bf16x2(v02 - bflo(ah2), v03 - bfhi(ah2));
        uint32_t al3 = pack_bf16x2(v12 - bflo(ah3), v13 - bfhi(ah3));

        float hc[16][4];
#pragma unroll
        for (int t = 0; t < 16; t++)
#pragma unroll
            for (int c = 0; c < 4; c++) hc[t][c] = 0.f;

#pragma unroll
        for (int ntp = 0; ntp < 8; ntp++) {
            uint32_t rb = (uint32_t)(wh * 128 + ntp * 16) * 48 + roffB;
            uint32_t b0, b1, b2, b3, l0, l1, l2, l3;
            ldm_x4(sBh_b + rb, b0, b1, b2, b3);
            ldm_x4(sBl_b + rb, l0, l1, l2, l3);
            float* c0 = hc[2 * ntp];
            float* c1 = hc[2 * ntp + 1];
            mma_bf16(c0, ah0, ah1, ah2, ah3, b0, b2);
            mma_bf16(c0, ah0, ah1, ah2, ah3, l0, l2);
            mma_bf16(c0, al0, al1, al2, al3, b0, b2);
            mma_bf16(c1, ah0, ah1, ah2, ah3, b1, b3);
            mma_bf16(c1, ah0, ah1, ah2, ah3, l1, l3);
            mma_bf16(c1, al0, al1, al2, al3, b1, b3);
        }
        // bias + relu + split + store
#pragma unroll
        for (int nt = 0; nt < 16; nt++) {
            int nc = wh * 128 + nt * 8 + 2 * t4;
            float b0v = s_b1[nc], b1v = s_b1[nc + 1];
            float u0 = fmaxf(hc[nt][0] + b0v, 0.f);
            float u1 = fmaxf(hc[nt][1] + b1v, 0.f);
            float u2 = fmaxf(hc[nt][2] + b0v, 0.f);
            float u3 = fmaxf(hc[nt][3] + b1v, 0.f);
            uint32_t h01 = pack_bf16x2(u0, u1);
            uint32_t h23 = pack_bf16x2(u2, u3);
            uint32_t q01 = pack_bf16x2(u0 - bflo(h01), u1 - bfhi(h01));
            uint32_t q23 = pack_bf16x2(u2 - bflo(h23), u3 - bfhi(h23));
            *reinterpret_cast<uint32_t*>(sm + OFF_AH + r0 * 528 + nc * 2) = h01;
            *reinterpret_cast<uint32_t*>(sm + OFF_AL + r0 * 528 + nc * 2) = q01;
            *reinterpret_cast<uint32_t*>(sm + OFF_AH + r1 * 528 + nc * 2) = h23;
            *reinterpret_cast<uint32_t*>(sm + OFF_AL + r1 * 528 + nc * 2) = q23;
        }
    }
    __syncthreads();   // sA ready; we1 tiles in sB fully consumed

    // ---- phase 2: e_proj GEMM ----
    const int we_ = (w >> 2) * 32, wn = (w & 3) * (TN / 4);
    float acc[2][NFW][4];
#pragma unroll
    for (int ti = 0; ti < 2; ti++)
#pragma unroll
        for (int f = 0; f < NFW; f++)
#pragma unroll
            for (int c = 0; c < 4; c++) acc[ti][f][c] = 0.f;

    for (int kc = 0; kc < HID; kc += 16) {
        // load weight chunk (n-major, 16 bf16 per row)
        for (int i = tid; i < TN * 2; i += 256) {
            int n = i >> 1, h = i & 1;
            *reinterpret_cast<uint4*>(sm + OFF_BH + n * 48 + h * 16) =
                *reinterpret_cast<const uint4*>(WhT + (size_t)n * HID + kc + h * 8);
            *reinterpret_cast<uint4*>(sm + OFF_BL + n * 48 + h * 16) =
                *reinterpret_cast<const uint4*>(WlT + (size_t)n * HID + kc + h * 8);
        }
        __syncthreads();
        uint32_t AH[2][4], AL[2][4];
#pragma unroll
        for (int ti = 0; ti < 2; ti++) {
            uint32_t ra = (uint32_t)(we_ + ti * 16) * 528 + (uint32_t)kc * 2 + roffA;
            ldm_x4(sAh_b + ra, AH[ti][0], AH[ti][1], AH[ti][2], AH[ti][3]);
            ldm_x4(sAl_b + ra, AL[ti][0], AL[ti][1], AL[ti][2], AL[ti][3]);
        }
#pragma unroll
        for (int nfp = 0; nfp < NFW / 2; nfp++) {
            uint32_t rb = (uint32_t)(wn + nfp * 16) * 48 + roffB;
            uint32_t bh0, bh1, bh2, bh3, bl0, bl1, bl2, bl3;
            ldm_x4(sBh_b + rb, bh0, bh1, bh2, bh3);
            ldm_x4(sBl_b + rb, bl0, bl1, bl2, bl3);
#pragma unroll
            for (int ti = 0; ti < 2; ti++) {
                float* c0 = acc[ti][2 * nfp];
                float* c1 = acc[ti][2 * nfp + 1];
                mma_bf16(c0, AH[ti][0], AH[ti][1], AH[ti][2], AH[ti][3], bh0, bh2);
                mma_bf16(c0, AH[ti][0], AH[ti][1], AH[ti][2], AH[ti][3], bl0, bl2);
                mma_bf16(c0, AL[ti][0], AL[ti][1], AL[ti][2], AL[ti][3], bh0, bh2);
                mma_bf16(c1, AH[ti][0], AH[ti][1], AH[ti][2], AH[ti][3], bh1, bh3);
                mma_bf16(c1, AH[ti][0], AH[ti][1], AH[ti][2], AH[ti][3], bl1, bl3);
                mma_bf16(c1, AL[ti][0], AL[ti][1], AL[ti][2], AL[ti][3], bh1, bh3);
            }
        }
        __syncthreads();
    }

    // ---- epilogue (validated R8 pattern) ----
#pragma unroll
    for (int ti = 0; ti < 2; ti++) {
        int er0 = we_ + ti * 16 + g, er1 = er0 + 8;
        int s0 = s_src[er0], d0 = s_dst[er0];
        int s1 = s_src[er1], d1 = s_dst[er1];
#pragma unroll
        for (int f = 0; f < NFW; f++) {
            int nc = wn + (f >> 1) * 16 + (f & 1) * 8 + 2 * t4;
            float b0v = bfb[nc], b1v = bfb[nc + 1];
            float2 x0 = *reinterpret_cast<const float2*>(xp + (size_t)s0 * CIN + nc);
            float2 x1 = *reinterpret_cast<const float2*>(xp + (size_t)s1 * CIN + nc);
            float* a0p = agg + (size_t)d0 * CIN + nc;
            float* a1p = agg + (size_t)d1 * CIN + nc;
            atomicAdd(a0p,     fmaxf(acc[ti][f][0] + b0v + x0.x, 0.f));
            atomicAdd(a0p + 1, fmaxf(acc[ti][f][1] + b1v + x0.y, 0.f));
            atomicAdd(a1p,     fmaxf(acc[ti][f][2] + b0v + x1.x, 0.f));
            atomicAdd(a1p + 1, fmaxf(acc[ti][f][3] + b1v + x1.y, 0.f));
        }
    }
}

// ---------------- node MLP GEMM (fp32, proven) ---------------------------------------
template <int K, int SEL>
__global__ void __launch_bounds__(256) node_mlp(const float* __restrict__ xin_param,
                                                const float* __restrict__ W,
                                                const float* __restrict__ b) {
    constexpr int TM = 64, TN = 128, KC = 32;
    constexpr bool HAS2 = (SEL == 0 || SEL == 2);
    const float* A1 = (SEL == 0) ? xin_param : (SEL == 2 ? g_x1 : g_tmp);
    const float* A2 = (SEL == 0) ? g_agg0 : g_agg1;
    float* out = (SEL == 0 || SEL == 2) ? g_tmp : (SEL == 1 ? g_x1 : g_x2);

    __shared__ float s_A[KC][TM + 1];
    __shared__ __align__(16) float s_B[KC][TN];
    int tid = threadIdx.x, cx = tid & 31, cy = tid >> 5;
    int m0 = blockIdx.x * TM, n0 = blockIdx.y * TN;
    float acc[8][4] = {};

    for (int kc = 0; kc < K; kc += KC) {
        __syncthreads();
        for (int i = tid; i < KC * TM; i += 256) {
            int k = i % KC, m = i / KC, gm = m0 + m;
            float v = 0.f;
            if (gm < NN) {
                v = A1[(size_t)gm * K + kc + k];
                if constexpr (HAS2) v += A2[(size_t)gm * K + kc + k];
            }
            s_A[k][m] = v;
        }
        for (int i = tid; i < KC * TN / 4; i += 256) {
            int k = i / (TN / 4), nq = i % (TN / 4);
            reinterpret_cast<float4*>(&s_B[k][0])[nq] =
                reinterpret_cast<const float4*>(W + (size_t)(kc + k) * HID + n0)[nq];
        }
        __syncthreads();
#pragma unroll
        for (int k = 0; k < KC; k++) {
            float bb[4];
#pragma unroll
            for (int i = 0; i < 4; i++) bb[i] = s_B[k][cx + 32 * i];
#pragma unroll
            for (int j = 0; j < 8; j++) {
                float a = s_A[k][cy * 8 + j];
#pragma unroll
                for (int i = 0; i < 4; i++) acc[j][i] = fmaf(a, bb[i], acc[j][i]);
            }
        }
    }
#pragma unroll
    for (int j = 0; j < 8; j++) {
        int m = m0 + cy * 8 + j;
        if (m < NN) {
#pragma unroll
            for (int i = 0; i < 4; i++) {
                int n = n0 + cx + 32 * i;
                out[(size_t)m * HID + n] = fmaxf(acc[j][i] + b[n], 0.f);
            }
        }
    }
}

// ---------------- pooling ------------------------------------------------------------
__global__ void zero_out(float* out) {
    int i = blockIdx.x * 256 + threadIdx.x;
    if (i < GG * HID) out[i] = 0.f;
    if (i < GG) g_cnt[i] = 0.f;
}
__global__ void pool_count(const int* __restrict__ batch) {
    int i = blockIdx.x * 256 + threadIdx.x;
    if (i < NN) atomicAdd(&g_cnt[batch[i]], 1.f);
}
__global__ void pool_accum(const int* __restrict__ batch, float* out) {
    int c = threadIdx.x;
    int nb = blockIdx.x * 8;
#pragma unroll
    for (int j = 0; j < 8; j++) {
        int node = nb + j;
        if (node < NN) {
            int g = batch[node];
            atomicAdd(&out[g * HID + c], g_x2[(size_t)node * HID + c]);
        }
    }
}
__global__ void pool_div(float* out) {
    int i = blockIdx.x * 256 + threadIdx.x;
    if (i < GG * HID) out[i] /= fmaxf(g_cnt[i / HID], 1.f);
}

// ---------------- launch -------------------------------------------------------------
extern "C" void kernel_launch(void* const* d_in, const int* in_sizes, int n_in,
                              void* d_out, int out_size) {
    const float* x     = (const float*)d_in[0];
    const float* ea    = (const float*)d_in[1];
    const int*   eidx  = (const int*)d_in[2];   // [2, E] int32 (JAX x64 disabled)
    const int*   batch = (const int*)d_in[3];
    const float* we1 = (const float*)d_in[4];
    const float* be1 = (const float*)d_in[5];
    const float* we2 = (const float*)d_in[6];
    const float* be2 = (const float*)d_in[7];
    const float* l0_lw = (const float*)d_in[8];
    const float* l0_lb = (const float*)d_in[9];
    const float* l0_w1 = (const float*)d_in[10];
    const float* l0_b1 = (const float*)d_in[11];
    const float* l0_w2 = (const float*)d_in[12];
    const float* l0_b2 = (const float*)d_in[13];
    const float* l1_lw = (const float*)d_in[14];
    const float* l1_lb = (const float*)d_in[15];
    const float* l1_w1 = (const float*)d_in[16];
    const float* l1_b1 = (const float*)d_in[17];
    const float* l1_w2 = (const float*)d_in[18];
    const float* l1_b2 = (const float*)d_in[19];
    const int* src = eidx;
    const int* dst = eidx + EE;
    float* out = (float*)d_out;

    static bool attr_done = false;
    if (!attr_done) {
        cudaFuncSetAttribute(conv_tc<0>, cudaFuncAttributeMaxDynamicSharedMemorySize,
                             CONV_SMEM);
        cudaFuncSetAttribute(conv_tc<1>, cudaFuncAttributeMaxDynamicSharedMemorySize,
                             CONV_SMEM);
        attr_done = true;
    }

    fuse_weights<<<HID, HID>>>(we1, we2, be2, l0_lw, l0_lb, l1_lw, l1_lb);
    zero_aggs<<<2048, 256>>>();

    // conv 0
    conv_tc<0><<<EE / 64, 256, CONV_SMEM>>>(ea, src, dst, be1, x);
    node_mlp<64, 0><<<dim3((NN + 63) / 64, 2), 256>>>(x, l0_w1, l0_b1);
    node_mlp<256, 1><<<dim3((NN + 63) / 64, 2), 256>>>(nullptr, l0_w2, l0_b2);

    // conv 1
    conv_tc<1><<<EE / 64, 256, CONV_SMEM>>>(ea, src, dst, be1, nullptr);
    node_mlp<256, 2><<<dim3((NN + 63) / 64, 2), 256>>>(nullptr, l1_w1, l1_b1);
    node_mlp<256, 3><<<dim3((NN + 63) / 64, 2), 256>>>(nullptr, l1_w2, l1_b2);

    // mean pool per graph
    zero_out<<<64, 256>>>(out);
    pool_count<<<(NN + 255) / 256, 256>>>(batch);
    pool_accum<<<(NN + 7) / 8, 256>>>(batch, out);
    pool_div<<<(GG * HID + 255) / 256, 256>>>(out);
}

// round 11
// speedup vs baseline: 1.6904x; 1.0570x over previous
#include <cuda_runtime.h>
#include <cuda_bf16.h>
#include <cstdint>

#define NN   10000
#define EE   320000
#define GG   64
#define NIN  64
#define EIN  16
#define HID  256

typedef __nv_bfloat16 bf16;

// ---------------- mma / ldmatrix helpers --------------------------------------------
__device__ __forceinline__ void ldm_x4(uint32_t addr, uint32_t& r0, uint32_t& r1,
                                       uint32_t& r2, uint32_t& r3) {
    asm volatile("ldmatrix.sync.aligned.m8n8.x4.shared.b16 {%0,%1,%2,%3}, [%4];"
                 : "=r"(r0), "=r"(r1), "=r"(r2), "=r"(r3) : "r"(addr));
}
__device__ __forceinline__ void mma_bf16(float c[4], uint32_t a0, uint32_t a1,
                                         uint32_t a2, uint32_t a3, uint32_t b0,
                                         uint32_t b1) {
    asm volatile(
        "mma.sync.aligned.m16n8k16.row.col.f32.bf16.bf16.f32 "
        "{%0,%1,%2,%3}, {%4,%5,%6,%7}, {%8,%9}, {%0,%1,%2,%3};"
        : "+f"(c[0]), "+f"(c[1]), "+f"(c[2]), "+f"(c[3])
        : "r"(a0), "r"(a1), "r"(a2), "r"(a3), "r"(b0), "r"(b1));
}
// pack (x -> low half, y -> high half) as bf16x2
__device__ __forceinline__ uint32_t pack_bf16x2(float x, float y) {
    uint32_t u;
    asm("cvt.rn.bf16x2.f32 %0, %1, %2;" : "=r"(u) : "f"(y), "f"(x));
    return u;
}
__device__ __forceinline__ float bflo(uint32_t u) { return __uint_as_float(u << 16); }
__device__ __forceinline__ float bfhi(uint32_t u) { return __uint_as_float(u & 0xffff0000u); }

// ---------------- scratch (__device__ globals; no allocation allowed) ----------------
__device__ __align__(16) bf16  g_W0hT[NIN * HID], g_W0lT[NIN * HID];  // (we2@l0_lw)^T split
__device__ __align__(16) bf16  g_W1hT[HID * HID], g_W1lT[HID * HID];  // (we2@l1_lw)^T split
__device__ __align__(16) bf16  g_we1hT[HID * EIN], g_we1lT[HID * EIN];  // we1^T split [n][k]
__device__ __align__(16) float g_b0f[NIN];
__device__ __align__(16) float g_b1f[HID];
__device__ __align__(16) float g_agg0[NN * NIN];
__device__ __align__(16) float g_agg1[NN * HID];
__device__ __align__(16) float g_x1[NN * HID];
__device__ __align__(16) float g_tmp[NN * HID];
__device__ __align__(16) float g_x2[NN * HID];
__device__ float g_cnt[GG];

// ---------------- weight pre-products -> transposed bf16 splits ----------------------
__global__ void fuse_weights(const float* __restrict__ we1,
                             const float* __restrict__ we2, const float* __restrict__ be2,
                             const float* __restrict__ l0_lw, const float* __restrict__ l0_lb,
                             const float* __restrict__ l1_lw, const float* __restrict__ l1_lb) {
    __shared__ float s_w[HID];
    int k = blockIdx.x;      // hidden row of we2
    int n = threadIdx.x;     // output col
    s_w[n] = we2[k * HID + n];
    __syncthreads();
    float acc = 0.f;
    for (int j = 0; j < HID; j++) acc += s_w[j] * l1_lw[j * HID + n];
    bf16 h1 = __float2bfloat16_rn(acc);
    g_W1hT[(size_t)n * HID + k] = h1;
    g_W1lT[(size_t)n * HID + k] = __float2bfloat16_rn(acc - __bfloat162float(h1));
    if (n < NIN) {
        float a0 = 0.f;
        for (int j = 0; j < HID; j++) a0 += s_w[j] * l0_lw[j * NIN + n];
        bf16 h0 = __float2bfloat16_rn(a0);
        g_W0hT[(size_t)n * HID + k] = h0;
        g_W0lT[(size_t)n * HID + k] = __float2bfloat16_rn(a0 - __bfloat162float(h0));
    }
    if (k < EIN) {   // we1 split, n-major [n][k]
        float v = we1[k * HID + n];
        bf16 hh = __float2bfloat16_rn(v);
        g_we1hT[(size_t)n * EIN + k] = hh;
        g_we1lT[(size_t)n * EIN + k] = __float2bfloat16_rn(v - __bfloat162float(hh));
    }
    if (k == 0) {
        float bb = 0.f;
        for (int j = 0; j < HID; j++) bb += be2[j] * l1_lw[j * HID + n];
        g_b1f[n] = bb + l1_lb[n];
        if (n < NIN) {
            float b0 = 0.f;
            for (int j = 0; j < HID; j++) b0 += be2[j] * l0_lw[j * NIN + n];
            g_b0f[n] = b0 + l0_lb[n];
        }
    }
}

__global__ void zero_aggs() {
    int i = blockIdx.x * 256 + threadIdx.x;
    int st = gridDim.x * 256;
    for (int j = i; j < NN * HID; j += st) g_agg1[j] = 0.f;
    for (int j = i; j < NN * NIN; j += st) g_agg0[j] = 0.f;
}

// ---------------- smem layout for conv kernel (dynamic) ------------------------------
#define OFF_AH  0
#define OFF_AL  33792
#define OFF_BH  67584
#define OFF_BL  79872
#define OFF_EA  92160
#define OFF_B1  97280
#define OFF_SRC 98304
#define OFF_DST 98560
#define CONV_SMEM 98816

// ---------------- fused edge conv: all-tensor-core, prefetched weights ---------------
// Phase 1: H[64x256] = relu(ea@we1 + be1) via bf16x3 mma, split hi/lo into sAh/sAl.
// Phase 2: e_proj = H @ Wf, KC=16 chunks; next chunk's weights prefetched into
//          registers while mma runs on the current chunk (L2 latency/BW overlapped).
// Epilogue: msg = relu(x[src] + e_proj + bias) -> atomicAdd agg[dst].
template <int CONV>
__global__ void __launch_bounds__(256, 2) conv_tc(const float* __restrict__ ea,
                                                  const int* __restrict__ src,
                                                  const int* __restrict__ dst,
                                                  const float* __restrict__ be1,
                                                  const float* __restrict__ xin_param) {
    constexpr int CIN = CONV ? HID : NIN;
    constexpr int TN  = CIN;
    constexpr int NFW = TN / 32;            // n8 frags per warp in phase 2
    constexpr int NPF = (TN * 2 + 255) / 256;  // prefetch iters (2 for 256, 1 for 64)
    extern __shared__ __align__(16) char sm[];
    const bf16* WhT = CONV ? g_W1hT : g_W0hT;
    const bf16* WlT = CONV ? g_W1lT : g_W0lT;
    const float* bfb = CONV ? g_b1f : g_b0f;
    const float* xp  = CONV ? g_x1 : xin_param;
    float* agg       = CONV ? g_agg1 : g_agg0;

    float (*s_ea)[20] = reinterpret_cast<float(*)[20]>(sm + OFF_EA);
    float* s_b1 = reinterpret_cast<float*>(sm + OFF_B1);
    int* s_src = reinterpret_cast<int*>(sm + OFF_SRC);
    int* s_dst = reinterpret_cast<int*>(sm + OFF_DST);

    const int tid = threadIdx.x;
    const int lane = tid & 31, w = tid >> 5;
    const int g = lane >> 2, t4 = lane & 3;
    const int e0 = blockIdx.x * 64;

    // one-time loads
    if (tid < 64) {
        s_src[tid] = src[e0 + tid];
        s_dst[tid] = dst[e0 + tid];
    }
    {
        int e = tid >> 2, q = (tid & 3) * 4;
        float4 v = *reinterpret_cast<const float4*>(ea + (size_t)(e0 + e) * EIN + q);
        s_ea[e][q] = v.x; s_ea[e][q + 1] = v.y; s_ea[e][q + 2] = v.z; s_ea[e][q + 3] = v.w;
    }
    s_b1[tid] = be1[tid];
    // we1^T split tiles into sB buffers (256 rows x 16 bf16 = 2x16B per row)
    for (int i = tid; i < 512; i += 256) {
        int n = i >> 1, h = i & 1;
        *reinterpret_cast<uint4*>(sm + OFF_BH + n * 48 + h * 16) =
            *reinterpret_cast<const uint4*>(g_we1hT + (size_t)n * EIN + h * 8);
        *reinterpret_cast<uint4*>(sm + OFF_BL + n * 48 + h * 16) =
            *reinterpret_cast<const uint4*>(g_we1lT + (size_t)n * EIN + h * 8);
    }

    // prefetch phase-2 weight chunk 0 into registers (L2 latency hidden by phase 1)
    uint4 pb[2 * NPF];
#pragma unroll
    for (int j = 0; j < NPF; j++) {
        int i = tid + 256 * j;
        if (i < TN * 2) {
            int n = i >> 1, h = i & 1;
            pb[2 * j]     = *reinterpret_cast<const uint4*>(WhT + (size_t)n * HID + h * 8);
            pb[2 * j + 1] = *reinterpret_cast<const uint4*>(WlT + (size_t)n * HID + h * 8);
        }
    }
    __syncthreads();

    const uint32_t sAh_b = (uint32_t)__cvta_generic_to_shared(sm + OFF_AH);
    const uint32_t sAl_b = (uint32_t)__cvta_generic_to_shared(sm + OFF_AL);
    const uint32_t sBh_b = (uint32_t)__cvta_generic_to_shared(sm + OFF_BH);
    const uint32_t sBl_b = (uint32_t)__cvta_generic_to_shared(sm + OFF_BL);
    const uint32_t roffB = (uint32_t)(lane & 15) * 48 + (uint32_t)(lane >> 4) * 16;
    const uint32_t roffA = (uint32_t)(lane & 15) * 528 + (uint32_t)(lane >> 4) * 16;

    // ---- phase 1: hidden tile via mma ----
    {
        const int wr = w >> 1, wh = w & 1;      // row-tile 0..3, col half 0..1
        const int r0 = wr * 16 + g, r1 = r0 + 8;
        float v00 = s_ea[r0][2 * t4],     v01 = s_ea[r0][2 * t4 + 1];
        float v10 = s_ea[r1][2 * t4],     v11 = s_ea[r1][2 * t4 + 1];
        float v02 = s_ea[r0][8 + 2 * t4], v03 = s_ea[r0][9 + 2 * t4];
        float v12 = s_ea[r1][8 + 2 * t4], v13 = s_ea[r1][9 + 2 * t4];
        uint32_t ah0 = pack_bf16x2(v00, v01), ah1 = pack_bf16x2(v10, v11);
        uint32_t ah2 = pack_bf16x2(v02, v03), ah3 = pack_bf16x2(v12, v13);
        uint32_t al0 = pack_bf16x2(v00 - bflo(ah0), v01 - bfhi(ah0));
        uint32_t al1 = pack_bf16x2(v10 - bflo(ah1), v11 - bfhi(ah1));
        uint32_t al2 = pack_bf16x2(v02 - bflo(ah2), v03 - bfhi(ah2));
        uint32_t al3 = pack_bf16x2(v12 - bflo(ah3), v13 - bfhi(ah3));

        float hc[16][4];
#pragma unroll
        for (int t = 0; t < 16; t++)
#pragma unroll
            for (int c = 0; c < 4; c++) hc[t][c] = 0.f;

#pragma unroll
        for (int ntp = 0; ntp < 8; ntp++) {
            uint32_t rb = (uint32_t)(wh * 128 + ntp * 16) * 48 + roffB;
            uint32_t b0, b1, b2, b3, l0, l1, l2, l3;
            ldm_x4(sBh_b + rb, b0, b1, b2, b3);
            ldm_x4(sBl_b + rb, l0, l1, l2, l3);
            float* c0 = hc[2 * ntp];
            float* c1 = hc[2 * ntp + 1];
            mma_bf16(c0, ah0, ah1, ah2, ah3, b0, b2);
            mma_bf16(c0, ah0, ah1, ah2, ah3, l0, l2);
            mma_bf16(c0, al0, al1, al2, al3, b0, b2);
            mma_bf16(c1, ah0, ah1, ah2, ah3, b1, b3);
            mma_bf16(c1, ah0, ah1, ah2, ah3, l1, l3);
            mma_bf16(c1, al0, al1, al2, al3, b1, b3);
        }
        // bias + relu + split + store
#pragma unroll
        for (int nt = 0; nt < 16; nt++) {
            int nc = wh * 128 + nt * 8 + 2 * t4;
            float b0v = s_b1[nc], b1v = s_b1[nc + 1];
            float u0 = fmaxf(hc[nt][0] + b0v, 0.f);
            float u1 = fmaxf(hc[nt][1] + b1v, 0.f);
            float u2 = fmaxf(hc[nt][2] + b0v, 0.f);
            float u3 = fmaxf(hc[nt][3] + b1v, 0.f);
            uint32_t h01 = pack_bf16x2(u0, u1);
            uint32_t h23 = pack_bf16x2(u2, u3);
            uint32_t q01 = pack_bf16x2(u0 - bflo(h01), u1 - bfhi(h01));
            uint32_t q23 = pack_bf16x2(u2 - bflo(h23), u3 - bfhi(h23));
            *reinterpret_cast<uint32_t*>(sm + OFF_AH + r0 * 528 + nc * 2) = h01;
            *reinterpret_cast<uint32_t*>(sm + OFF_AL + r0 * 528 + nc * 2) = q01;
            *reinterpret_cast<uint32_t*>(sm + OFF_AH + r1 * 528 + nc * 2) = h23;
            *reinterpret_cast<uint32_t*>(sm + OFF_AL + r1 * 528 + nc * 2) = q23;
        }
    }

    // ---- phase 2: e_proj GEMM with register-prefetched weight chunks ----
    const int we_ = (w >> 2) * 32, wn = (w & 3) * (TN / 4);
    float acc[2][NFW][4];
#pragma unroll
    for (int ti = 0; ti < 2; ti++)
#pragma unroll
        for (int f = 0; f < NFW; f++)
#pragma unroll
            for (int c = 0; c < 4; c++) acc[ti][f][c] = 0.f;

    for (int kc = 0; kc < HID; kc += 16) {
        __syncthreads();   // prior consumers of sB done (phase 1 / previous chunk ldm)
        // commit prefetched chunk to smem
#pragma unroll
        for (int j = 0; j < NPF; j++) {
            int i = tid + 256 * j;
            if (i < TN * 2) {
                int n = i >> 1, h = i & 1;
                *reinterpret_cast<uint4*>(sm + OFF_BH + n * 48 + h * 16) = pb[2 * j];
                *reinterpret_cast<uint4*>(sm + OFF_BL + n * 48 + h * 16) = pb[2 * j + 1];
            }
        }
        // start loading NEXT chunk (latency overlapped with mma below)
        if (kc + 16 < HID) {
#pragma unroll
            for (int j = 0; j < NPF; j++) {
                int i = tid + 256 * j;
                if (i < TN * 2) {
                    int n = i >> 1, h = i & 1;
                    pb[2 * j] = *reinterpret_cast<const uint4*>(
                        WhT + (size_t)n * HID + kc + 16 + h * 8);
                    pb[2 * j + 1] = *reinterpret_cast<const uint4*>(
                        WlT + (size_t)n * HID + kc + 16 + h * 8);
                }
            }
        }
        __syncthreads();   // sB ready
        uint32_t AH[2][4], AL[2][4];
#pragma unroll
        for (int ti = 0; ti < 2; ti++) {
            uint32_t ra = (uint32_t)(we_ + ti * 16) * 528 + (uint32_t)kc * 2 + roffA;
            ldm_x4(sAh_b + ra, AH[ti][0], AH[ti][1], AH[ti][2], AH[ti][3]);
            ldm_x4(sAl_b + ra, AL[ti][0], AL[ti][1], AL[ti][2], AL[ti][3]);
        }
#pragma unroll
        for (int nfp = 0; nfp < NFW / 2; nfp++) {
            uint32_t rb = (uint32_t)(wn + nfp * 16) * 48 + roffB;
            uint32_t bh0, bh1, bh2, bh3, bl0, bl1, bl2, bl3;
            ldm_x4(sBh_b + rb, bh0, bh1, bh2, bh3);
            ldm_x4(sBl_b + rb, bl0, bl1, bl2, bl3);
#pragma unroll
            for (int ti = 0; ti < 2; ti++) {
                float* c0 = acc[ti][2 * nfp];
                float* c1 = acc[ti][2 * nfp + 1];
                mma_bf16(c0, AH[ti][0], AH[ti][1], AH[ti][2], AH[ti][3], bh0, bh2);
                mma_bf16(c0, AH[ti][0], AH[ti][1], AH[ti][2], AH[ti][3], bl0, bl2);
                mma_bf16(c0, AL[ti][0], AL[ti][1], AL[ti][2], AL[ti][3], bh0, bh2);
                mma_bf16(c1, AH[ti][0], AH[ti][1], AH[ti][2], AH[ti][3], bh1, bh3);
                mma_bf16(c1, AH[ti][0], AH[ti][1], AH[ti][2], AH[ti][3], bl1, bl3);
                mma_bf16(c1, AL[ti][0], AL[ti][1], AL[ti][2], AL[ti][3], bh1, bh3);
            }
        }
    }

    // ---- epilogue ----
#pragma unroll
    for (int ti = 0; ti < 2; ti++) {
        int er0 = we_ + ti * 16 + g, er1 = er0 + 8;
        int s0 = s_src[er0], d0 = s_dst[er0];
        int s1 = s_src[er1], d1 = s_dst[er1];
#pragma unroll
        for (int f = 0; f < NFW; f++) {
            int nc = wn + (f >> 1) * 16 + (f & 1) * 8 + 2 * t4;
            float b0v = bfb[nc], b1v = bfb[nc + 1];
            float2 x0 = *reinterpret_cast<const float2*>(xp + (size_t)s0 * CIN + nc);
            float2 x1 = *reinterpret_cast<const float2*>(xp + (size_t)s1 * CIN + nc);
            float* a0p = agg + (size_t)d0 * CIN + nc;
            float* a1p = agg + (size_t)d1 * CIN + nc;
            atomicAdd(a0p,     fmaxf(acc[ti][f][0] + b0v + x0.x, 0.f));
            atomicAdd(a0p + 1, fmaxf(acc[ti][f][1] + b1v + x0.y, 0.f));
            atomicAdd(a1p,     fmaxf(acc[ti][f][2] + b0v + x1.x, 0.f));
            atomicAdd(a1p + 1, fmaxf(acc[ti][f][3] + b1v + x1.y, 0.f));
        }
    }
}

// ---------------- node MLP GEMM (fp32, proven) ---------------------------------------
template <int K, int SEL>
__global__ void __launch_bounds__(256) node_mlp(const float* __restrict__ xin_param,
                                                const float* __restrict__ W,
                                                const float* __restrict__ b) {
    constexpr int TM = 64, TN = 128, KC = 32;
    constexpr bool HAS2 = (SEL == 0 || SEL == 2);
    const float* A1 = (SEL == 0) ? xin_param : (SEL == 2 ? g_x1 : g_tmp);
    const float* A2 = (SEL == 0) ? g_agg0 : g_agg1;
    float* out = (SEL == 0 || SEL == 2) ? g_tmp : (SEL == 1 ? g_x1 : g_x2);

    __shared__ float s_A[KC][TM + 1];
    __shared__ __align__(16) float s_B[KC][TN];
    int tid = threadIdx.x, cx = tid & 31, cy = tid >> 5;
    int m0 = blockIdx.x * TM, n0 = blockIdx.y * TN;
    float acc[8][4] = {};

    for (int kc = 0; kc < K; kc += KC) {
        __syncthreads();
        for (int i = tid; i < KC * TM; i += 256) {
            int k = i % KC, m = i / KC, gm = m0 + m;
            float v = 0.f;
            if (gm < NN) {
                v = A1[(size_t)gm * K + kc + k];
                if constexpr (HAS2) v += A2[(size_t)gm * K + kc + k];
            }
            s_A[k][m] = v;
        }
        for (int i = tid; i < KC * TN / 4; i += 256) {
            int k = i / (TN / 4), nq = i % (TN / 4);
            reinterpret_cast<float4*>(&s_B[k][0])[nq] =
                reinterpret_cast<const float4*>(W + (size_t)(kc + k) * HID + n0)[nq];
        }
        __syncthreads();
#pragma unroll
        for (int k = 0; k < KC; k++) {
            float bb[4];
#pragma unroll
            for (int i = 0; i < 4; i++) bb[i] = s_B[k][cx + 32 * i];
#pragma unroll
            for (int j = 0; j < 8; j++) {
                float a = s_A[k][cy * 8 + j];
#pragma unroll
                for (int i = 0; i < 4; i++) acc[j][i] = fmaf(a, bb[i], acc[j][i]);
            }
        }
    }
#pragma unroll
    for (int j = 0; j < 8; j++) {
        int m = m0 + cy * 8 + j;
        if (m < NN) {
#pragma unroll
            for (int i = 0; i < 4; i++) {
                int n = n0 + cx + 32 * i;
                out[(size_t)m * HID + n] = fmaxf(acc[j][i] + b[n], 0.f);
            }
        }
    }
}

// ---------------- pooling ------------------------------------------------------------
__global__ void zero_out(float* out) {
    int i = blockIdx.x * 256 + threadIdx.x;
    if (i < GG * HID) out[i] = 0.f;
    if (i < GG) g_cnt[i] = 0.f;
}
__global__ void pool_count(const int* __restrict__ batch) {
    int i = blockIdx.x * 256 + threadIdx.x;
    if (i < NN) atomicAdd(&g_cnt[batch[i]], 1.f);
}
__global__ void pool_accum(const int* __restrict__ batch, float* out) {
    int c = threadIdx.x;
    int nb = blockIdx.x * 8;
#pragma unroll
    for (int j = 0; j < 8; j++) {
        int node = nb + j;
        if (node < NN) {
            int g = batch[node];
            atomicAdd(&out[g * HID + c], g_x2[(size_t)node * HID + c]);
        }
    }
}
__global__ void pool_div(float* out) {
    int i = blockIdx.x * 256 + threadIdx.x;
    if (i < GG * HID) out[i] /= fmaxf(g_cnt[i / HID], 1.f);
}

// ---------------- launch -------------------------------------------------------------
extern "C" void kernel_launch(void* const* d_in, const int* in_sizes, int n_in,
                              void* d_out, int out_size) {
    const float* x     = (const float*)d_in[0];
    const float* ea    = (const float*)d_in[1];
    const int*   eidx  = (const int*)d_in[2];   // [2, E] int32 (JAX x64 disabled)
    const int*   batch = (const int*)d_in[3];
    const float* we1 = (const float*)d_in[4];
    const float* be1 = (const float*)d_in[5];
    const float* we2 = (const float*)d_in[6];
    const float* be2 = (const float*)d_in[7];
    const float* l0_lw = (const float*)d_in[8];
    const float* l0_lb = (const float*)d_in[9];
    const float* l0_w1 = (const float*)d_in[10];
    const float* l0_b1 = (const float*)d_in[11];
    const float* l0_w2 = (const float*)d_in[12];
    const float* l0_b2 = (const float*)d_in[13];
    const float* l1_lw = (const float*)d_in[14];
    const float* l1_lb = (const float*)d_in[15];
    const float* l1_w1 = (const float*)d_in[16];
    const float* l1_b1 = (const float*)d_in[17];
    const float* l1_w2 = (const float*)d_in[18];
    const float* l1_b2 = (const float*)d_in[19];
    const int* src = eidx;
    const int* dst = eidx + EE;
    float* out = (float*)d_out;

    static bool attr_done = false;
    if (!attr_done) {
        cudaFuncSetAttribute(conv_tc<0>, cudaFuncAttributeMaxDynamicSharedMemorySize,
                             CONV_SMEM);
        cudaFuncSetAttribute(conv_tc<1>, cudaFuncAttributeMaxDynamicSharedMemorySize,
                             CONV_SMEM);
        attr_done = true;
    }

    fuse_weights<<<HID, HID>>>(we1, we2, be2, l0_lw, l0_lb, l1_lw, l1_lb);
    zero_aggs<<<2048, 256>>>();

    // conv 0
    conv_tc<0><<<EE / 64, 256, CONV_SMEM>>>(ea, src, dst, be1, x);
    node_mlp<64, 0><<<dim3((NN + 63) / 64, 2), 256>>>(x, l0_w1, l0_b1);
    node_mlp<256, 1><<<dim3((NN + 63) / 64, 2), 256>>>(nullptr, l0_w2, l0_b2);

    // conv 1
    conv_tc<1><<<EE / 64, 256, CONV_SMEM>>>(ea, src, dst, be1, nullptr);
    node_mlp<256, 2><<<dim3((NN + 63) / 64, 2), 256>>>(nullptr, l1_w1, l1_b1);
    node_mlp<256, 3><<<dim3((NN + 63) / 64, 2), 256>>>(nullptr, l1_w2, l1_b2);

    // mean pool per graph
    zero_out<<<64, 256>>>(out);
    pool_count<<<(NN + 255) / 256, 256>>>(batch);
    pool_accum<<<(NN + 7) / 8, 256>>>(batch, out);
    pool_div<<<(GG * HID + 255) / 256, 256>>>(out);
}